// round 16
// baseline (speedup 1.0000x reference)
#include <cuda_runtime.h>
#include <math.h>
#include <stdint.h>

#define TT   2048
#define DD   512
#define HH   8
#define HDD  64
#define LLAY 4
#define HIDN 2048
#define EE   8
#define VV   32000
typedef long long ll;
typedef unsigned long long ull;

// ---------------- device scratch ----------------
__device__ float g_x[TT * DD];
__device__ float g_xn[TT * DD];
__device__ float g_q[TT * DD];
__device__ float g_k[TT * DD];
__device__ float g_v[TT * DD];
__device__ float g_attn[TT * DD];
__device__ float g_P[(ll)HH * TT * TT];
__device__ float g_G[TT * 2 * HIDN];
__device__ float g_U[TT * 2 * HIDN];
__device__ float g_Y[TT * 2 * DD];
__device__ float g_ew[TT * 2];
__device__ int   g_eidx[TT * 2];
__device__ int   g_counts[EE];
__device__ int   g_offs[EE];
__device__ int   g_cursor[EE];
__device__ int   g_perm[TT * 2];
__device__ int   g_slot[TT * 2];

// ---------------- f32x2 fp32 path (round-8 proven; PV only) ----------------
__device__ __forceinline__ ull pk2(float x) {
    ull r; uint32_t u = __float_as_uint(x);
    asm("mov.b64 %0, {%1, %1};" : "=l"(r) : "r"(u));
    return r;
}
__device__ __forceinline__ float2 up2(ull v) {
    uint32_t lo, hi;
    asm("mov.b64 {%0, %1}, %2;" : "=r"(lo), "=r"(hi) : "l"(v));
    return make_float2(__uint_as_float(lo), __uint_as_float(hi));
}
#define FMA2(c, a, b) asm("fma.rn.f32x2 %0, %1, %2, %0;" : "+l"(c) : "l"(a), "l"(b))

__device__ __forceinline__ void micro8(
    const float (*As)[128], const float (*Bs)[128],
    ull c[8][4], int ty, int tx)
{
#pragma unroll
    for (int kk = 0; kk < 8; kk++) {
        const float* ar = &As[kk][ty * 8];
        const ull* br = (const ull*)&Bs[kk][tx * 8];
        ull b0 = br[0], b1 = br[1], b2 = br[2], b3 = br[3];
#pragma unroll
        for (int i = 0; i < 8; i++) {
            ull ap = pk2(ar[i]);
            FMA2(c[i][0], ap, b0);
            FMA2(c[i][1], ap, b1);
            FMA2(c[i][2], ap, b2);
            FMA2(c[i][3], ap, b3);
        }
    }
}

#define FLAG_CAUSAL 1
#define FLAG_KCLIP  2

template <bool TRANSB>
__global__ __launch_bounds__(256, 2) void sgemm2(
    const float* __restrict__ A, int lda, ll sA,
    const float* __restrict__ B, int ldb, ll sB,
    float* __restrict__ C, int ldc, ll sC,
    const float* __restrict__ Res,
    int M, int N, int K, int flags)
{
    if ((flags & FLAG_CAUSAL) && (int)blockIdx.x > (int)blockIdx.y) return;

    const float* Ab = A + (ll)blockIdx.z * sA;
    const float* Bb = B + (ll)blockIdx.z * sB;
    float*       Cb = C + (ll)blockIdx.z * sC;
    const float* Rb = Res ? (Res + (ll)blockIdx.z * sC) : (const float*)0;

    const int bm = blockIdx.y * 128, bn = blockIdx.x * 128;
    const int tid = threadIdx.x;
    const int tx = tid & 15, ty = tid >> 4;

    __shared__ __align__(16) float As[8][128];
    __shared__ __align__(16) float Bs[8][128];

    ull c[8][4];
#pragma unroll
    for (int i = 0; i < 8; i++)
#pragma unroll
        for (int j = 0; j < 4; j++) c[i][j] = 0ull;

    const int kmax = (flags & FLAG_KCLIP) ? min(K, bm + 128) : K;

    for (int k0 = 0; k0 < kmax; k0 += 8) {
#pragma unroll
        for (int i = 0; i < 4; i++) {
            int idx = tid + i * 256;
            int m = idx >> 3, kk = idx & 7;
            int gm = bm + m;
            As[kk][m] = (gm < M) ? Ab[(ll)gm * lda + k0 + kk] : 0.f;
        }
#pragma unroll
        for (int i = 0; i < 4; i++) {
            int idx = tid + i * 256;
            if (TRANSB) {
                int n = idx >> 3, kk = idx & 7;
                int gn = bn + n;
                Bs[kk][n] = (gn < N) ? Bb[(ll)gn * ldb + k0 + kk] : 0.f;
            } else {
                int kk = idx >> 7, n = idx & 127;
                int gn = bn + n;
                Bs[kk][n] = (gn < N) ? Bb[(ll)(k0 + kk) * ldb + gn] : 0.f;
            }
        }
        __syncthreads();
        micro8(As, Bs, c, ty, tx);
        __syncthreads();
    }

#pragma unroll
    for (int i = 0; i < 8; i++) {
        int r = bm + ty * 8 + i;
        if (r >= M) continue;
#pragma unroll
        for (int j = 0; j < 4; j++) {
            int cc = bn + tx * 8 + j * 2;
            float2 v = up2(c[i][j]);
            if (cc < N) {
                float o = v.x;
                if (Rb) o += Rb[(ll)r * ldc + cc];
                Cb[(ll)r * ldc + cc] = o;
            }
            if (cc + 1 < N) {
                float o = v.y;
                if (Rb) o += Rb[(ll)r * ldc + cc + 1];
                Cb[(ll)r * ldc + cc + 1] = o;
            }
        }
    }
}

// ================= 2-term split TF32 mma machinery (validated) =============
__device__ __forceinline__ uint32_t f2tf(float x) {
    uint32_t r;
    asm("cvt.rna.tf32.f32 %0, %1;" : "=r"(r) : "f"(x));
    return r;
}
#define LSTR 36
#define MATW (128 * LSTR)
#define SMB2 (4 * MATW * 4)          // A hi/lo + B hi/lo = 73728 B

__device__ __forceinline__ void sts_split2(uint32_t* p, float4 v) {
    uint32_t hx = f2tf(v.x), hy = f2tf(v.y), hz = f2tf(v.z), hw = f2tf(v.w);
    *(uint4*)p = make_uint4(hx, hy, hz, hw);
    uint4 lo;
    lo.x = f2tf(v.x - __uint_as_float(hx));
    lo.y = f2tf(v.y - __uint_as_float(hy));
    lo.z = f2tf(v.z - __uint_as_float(hz));
    lo.w = f2tf(v.w - __uint_as_float(hw));
    *(uint4*)(p + MATW) = lo;
}
__device__ __forceinline__ void sts_split1(uint32_t* p, float x) {
    uint32_t h = f2tf(x);
    p[0]    = h;
    p[MATW] = f2tf(x - __uint_as_float(h));
}
__device__ __forceinline__ void mma8(float* c, const uint32_t* a, const uint32_t* b) {
    asm volatile(
        "mma.sync.aligned.m16n8k8.row.col.f32.tf32.tf32.f32 "
        "{%0,%1,%2,%3}, {%4,%5,%6,%7}, {%8,%9}, {%0,%1,%2,%3};"
        : "+f"(c[0]), "+f"(c[1]), "+f"(c[2]), "+f"(c[3])
        : "r"(a[0]), "r"(a[1]), "r"(a[2]), "r"(a[3]), "r"(b[0]), "r"(b[1]));
}

__device__ __forceinline__ void stage_mma2(
    const uint32_t* As, const uint32_t* Bs, float c[2][8][4],
    int wm, int wn, int g, int tg)
{
#pragma unroll
    for (int kk = 0; kk < 32; kk += 8) {
        uint32_t ah[2][4], al[2][4];
#pragma unroll
        for (int mt = 0; mt < 2; mt++) {
            const uint32_t* p = &As[(wm + mt * 16 + g) * LSTR + kk + tg];
            ah[mt][0] = p[0];          ah[mt][2] = p[4];
            ah[mt][1] = p[8 * LSTR];   ah[mt][3] = p[8 * LSTR + 4];
            const uint32_t* q = p + MATW;
            al[mt][0] = q[0];          al[mt][2] = q[4];
            al[mt][1] = q[8 * LSTR];   al[mt][3] = q[8 * LSTR + 4];
        }
#pragma unroll
        for (int nt = 0; nt < 8; nt++) {
            const uint32_t* p = &Bs[(wn + nt * 8 + g) * LSTR + kk + tg];
            uint32_t bh[2], bl[2];
            bh[0] = p[0];        bh[1] = p[4];
            bl[0] = p[MATW];     bl[1] = p[MATW + 4];
#pragma unroll
            for (int mt = 0; mt < 2; mt++) {
                mma8(c[mt][nt], al[mt], bh);
                mma8(c[mt][nt], ah[mt], bl);
                mma8(c[mt][nt], ah[mt], bh);
            }
        }
    }
}

// Conflict-free transposed-B split store (validated R15)
__device__ __forceinline__ void loadBT_cf(
    const float* __restrict__ Bb, int ldb, int bn, int k0,
    uint32_t* Bs, int wid, int lane)
{
    const int kk = wid * 4 + (lane & 3);
    const int nb = lane >> 2;
    const float* src = Bb + (ll)(k0 + kk) * ldb + bn + nb;
    uint32_t* dst = &Bs[nb * LSTR + kk];
#pragma unroll
    for (int j = 0; j < 16; j++)
        sts_split1(dst + j * 8 * LSTR, src[j * 8]);
}

// ---------------- LM head mma2 ----------------
__global__ __launch_bounds__(256, 2) void mm_gemm2(
    const float* __restrict__ A, int lda,
    const float* __restrict__ BT, int ldb,
    float* __restrict__ C, int ldc, int N, int K)
{
    const int bm = blockIdx.y * 128, bn = blockIdx.x * 128;

    extern __shared__ uint32_t sm[];
    uint32_t* As = sm;
    uint32_t* Bs = sm + 2 * MATW;

    const int tid = threadIdx.x, wid = tid >> 5, lane = tid & 31;
    const int g = lane >> 2, tg = lane & 3;
    const int wm = (wid >> 1) * 32, wn = (wid & 1) * 64;

    float c[2][8][4];
#pragma unroll
    for (int mt = 0; mt < 2; mt++)
#pragma unroll
        for (int nt = 0; nt < 8; nt++)
#pragma unroll
            for (int i = 0; i < 4; i++) c[mt][nt][i] = 0.f;

    for (int k0 = 0; k0 < K; k0 += 32) {
#pragma unroll
        for (int i = 0; i < 4; i++) {
            int idx = tid + i * 256;
            int m = idx >> 3, qq = idx & 7;
            float4 v = *(const float4*)(A + (ll)(bm + m) * lda + k0 + qq * 4);
            sts_split2(&As[m * LSTR + qq * 4], v);
        }
#pragma unroll
        for (int i = 0; i < 4; i++) {
            int idx = tid + i * 256;
            int n = idx >> 3, qq = idx & 7;
            float4 v = make_float4(0.f, 0.f, 0.f, 0.f);
            if (bn + n < N) v = *(const float4*)(BT + (ll)(bn + n) * ldb + k0 + qq * 4);
            sts_split2(&Bs[n * LSTR + qq * 4], v);
        }
        __syncthreads();
        stage_mma2(As, Bs, c, wm, wn, g, tg);
        __syncthreads();
    }

#pragma unroll
    for (int mt = 0; mt < 2; mt++)
#pragma unroll
        for (int nt = 0; nt < 8; nt++) {
            int r0 = bm + wm + mt * 16 + g;
            int cc = bn + wn + nt * 8 + tg * 2;
            if (cc < N) {
                *(float2*)(C + (ll)r0 * ldc + cc)       = make_float2(c[mt][nt][0], c[mt][nt][1]);
                *(float2*)(C + (ll)(r0 + 8) * ldc + cc) = make_float2(c[mt][nt][2], c[mt][nt][3]);
            }
        }
}

// ---------------- QKV via mma2 ----------------
__global__ __launch_bounds__(256, 2) void qkv_mma(
    const float* __restrict__ xn,
    const float* __restrict__ wq, const float* __restrict__ wk,
    const float* __restrict__ wv, int l)
{
    const int z = blockIdx.z;
    const float* Bb = (z == 0 ? wq : z == 1 ? wk : wv) + (ll)l * DD * DD;
    float* Cb = (z == 0 ? g_q : z == 1 ? g_k : g_v);

    const int bm = blockIdx.y * 128, bn = blockIdx.x * 128;
    extern __shared__ uint32_t sm[];
    uint32_t* As = sm;
    uint32_t* Bs = sm + 2 * MATW;

    const int tid = threadIdx.x, wid = tid >> 5, lane = tid & 31;
    const int g = lane >> 2, tg = lane & 3;
    const int wm = (wid >> 1) * 32, wn = (wid & 1) * 64;

    float c[2][8][4];
#pragma unroll
    for (int mt = 0; mt < 2; mt++)
#pragma unroll
        for (int nt = 0; nt < 8; nt++)
#pragma unroll
            for (int i = 0; i < 4; i++) c[mt][nt][i] = 0.f;

    for (int k0 = 0; k0 < DD; k0 += 32) {
#pragma unroll
        for (int i = 0; i < 4; i++) {
            int idx = tid + i * 256;
            int m = idx >> 3, qq = idx & 7;
            float4 v = *(const float4*)(xn + (ll)(bm + m) * DD + k0 + qq * 4);
            sts_split2(&As[m * LSTR + qq * 4], v);
        }
        loadBT_cf(Bb, DD, bn, k0, Bs, wid, lane);
        __syncthreads();
        stage_mma2(As, Bs, c, wm, wn, g, tg);
        __syncthreads();
    }

#pragma unroll
    for (int mt = 0; mt < 2; mt++)
#pragma unroll
        for (int nt = 0; nt < 8; nt++) {
            int r0 = bm + wm + mt * 16 + g;
            int cc = bn + wn + nt * 8 + tg * 2;
            *(float2*)(Cb + (ll)r0 * DD + cc)       = make_float2(c[mt][nt][0], c[mt][nt][1]);
            *(float2*)(Cb + (ll)(r0 + 8) * DD + cc) = make_float2(c[mt][nt][2], c[mt][nt][3]);
        }
}

// ---------------- wo via mma2 (residual into g_x) ----------------
__global__ __launch_bounds__(256, 2) void wo_mma(const float* __restrict__ wo, int l)
{
    const float* Bb = wo + (ll)l * DD * DD;
    const int bm = blockIdx.y * 128, bn = blockIdx.x * 128;
    extern __shared__ uint32_t sm[];
    uint32_t* As = sm;
    uint32_t* Bs = sm + 2 * MATW;

    const int tid = threadIdx.x, wid = tid >> 5, lane = tid & 31;
    const int g = lane >> 2, tg = lane & 3;
    const int wm = (wid >> 1) * 32, wn = (wid & 1) * 64;

    float c[2][8][4];
#pragma unroll
    for (int mt = 0; mt < 2; mt++)
#pragma unroll
        for (int nt = 0; nt < 8; nt++)
#pragma unroll
            for (int i = 0; i < 4; i++) c[mt][nt][i] = 0.f;

    for (int k0 = 0; k0 < DD; k0 += 32) {
#pragma unroll
        for (int i = 0; i < 4; i++) {
            int idx = tid + i * 256;
            int m = idx >> 3, qq = idx & 7;
            float4 v = *(const float4*)(g_attn + (ll)(bm + m) * DD + k0 + qq * 4);
            sts_split2(&As[m * LSTR + qq * 4], v);
        }
        loadBT_cf(Bb, DD, bn, k0, Bs, wid, lane);
        __syncthreads();
        stage_mma2(As, Bs, c, wm, wn, g, tg);
        __syncthreads();
    }

#pragma unroll
    for (int mt = 0; mt < 2; mt++)
#pragma unroll
        for (int nt = 0; nt < 8; nt++) {
            int r0 = bm + wm + mt * 16 + g;
            int cc = bn + wn + nt * 8 + tg * 2;
            float2* p0 = (float2*)(g_x + (ll)r0 * DD + cc);
            float2* p1 = (float2*)(g_x + (ll)(r0 + 8) * DD + cc);
            float2 v0 = *p0, v1 = *p1;
            v0.x += c[mt][nt][0]; v0.y += c[mt][nt][1];
            v1.x += c[mt][nt][2]; v1.y += c[mt][nt][3];
            *p0 = v0; *p1 = v1;
        }
}

// ---------------- attention scores via mma2 (causal block-skip) -------------
__global__ __launch_bounds__(256, 2) void score_mma()
{
    const int bm = blockIdx.y * 128, bn = blockIdx.x * 128;
    if (bn > bm) return;
    const int h = blockIdx.z;
    const float* Aq = g_q + h * HDD;
    const float* Bk = g_k + h * HDD;
    float* P = g_P + (ll)h * TT * TT;

    extern __shared__ uint32_t sm[];
    uint32_t* As = sm;
    uint32_t* Bs = sm + 2 * MATW;

    const int tid = threadIdx.x, wid = tid >> 5, lane = tid & 31;
    const int g = lane >> 2, tg = lane & 3;
    const int wm = (wid >> 1) * 32, wn = (wid & 1) * 64;

    float c[2][8][4];
#pragma unroll
    for (int mt = 0; mt < 2; mt++)
#pragma unroll
        for (int nt = 0; nt < 8; nt++)
#pragma unroll
            for (int i = 0; i < 4; i++) c[mt][nt][i] = 0.f;

#pragma unroll
    for (int k0 = 0; k0 < HDD; k0 += 32) {
#pragma unroll
        for (int i = 0; i < 4; i++) {
            int idx = tid + i * 256;
            int m = idx >> 3, qq = idx & 7;
            float4 v = *(const float4*)(Aq + (ll)(bm + m) * DD + k0 + qq * 4);
            sts_split2(&As[m * LSTR + qq * 4], v);
        }
#pragma unroll
        for (int i = 0; i < 4; i++) {
            int idx = tid + i * 256;
            int n = idx >> 3, qq = idx & 7;
            float4 v = *(const float4*)(Bk + (ll)(bn + n) * DD + k0 + qq * 4);
            sts_split2(&Bs[n * LSTR + qq * 4], v);
        }
        __syncthreads();
        stage_mma2(As, Bs, c, wm, wn, g, tg);
        __syncthreads();
    }

#pragma unroll
    for (int mt = 0; mt < 2; mt++)
#pragma unroll
        for (int nt = 0; nt < 8; nt++) {
            int r0 = bm + wm + mt * 16 + g;
            int cc = bn + wn + nt * 8 + tg * 2;
            *(float2*)(P + (ll)r0 * TT + cc)       = make_float2(c[mt][nt][0], c[mt][nt][1]);
            *(float2*)(P + (ll)(r0 + 8) * TT + cc) = make_float2(c[mt][nt][2], c[mt][nt][3]);
        }
}

// ---------------- MoE up via mma2 ----------------
__global__ __launch_bounds__(256, 2) void moeup_mma(
    const float* __restrict__ xn,
    const float* __restrict__ w1, const float* __restrict__ w3, int l)
{
    const int e = blockIdx.z >> 1, which = blockIdx.z & 1;
    const int cnt = g_counts[e];
    const int bm = blockIdx.y * 128;
    if (bm >= cnt) return;
    const int off = g_offs[e];
    const int bn = blockIdx.x * 128;

    const float* Bb = (which ? w3 : w1) + ((ll)l * EE + e) * DD * HIDN;
    float* Cb = which ? g_U : g_G;

    extern __shared__ uint32_t sm[];
    uint32_t* As = sm;
    uint32_t* Bs = sm + 2 * MATW;

    const int tid = threadIdx.x, wid = tid >> 5, lane = tid & 31;
    const int g = lane >> 2, tg = lane & 3;
    const int wm = (wid >> 1) * 32, wn = (wid & 1) * 64;

    const float* aptr[4];
    int av[4];
#pragma unroll
    for (int i = 0; i < 4; i++) {
        int m = (tid + i * 256) >> 3;
        av[i] = (bm + m) < cnt;
        aptr[i] = xn + (ll)(av[i] ? g_perm[off + bm + m] : 0) * DD;
    }

    float c[2][8][4];
#pragma unroll
    for (int mt = 0; mt < 2; mt++)
#pragma unroll
        for (int nt = 0; nt < 8; nt++)
#pragma unroll
            for (int i = 0; i < 4; i++) c[mt][nt][i] = 0.f;

    for (int k0 = 0; k0 < DD; k0 += 32) {
#pragma unroll
        for (int i = 0; i < 4; i++) {
            int idx = tid + i * 256;
            int m = idx >> 3, qq = idx & 7;
            float4 v = make_float4(0.f, 0.f, 0.f, 0.f);
            if (av[i]) v = *(const float4*)(aptr[i] + k0 + qq * 4);
            sts_split2(&As[m * LSTR + qq * 4], v);
        }
        loadBT_cf(Bb, HIDN, bn, k0, Bs, wid, lane);
        __syncthreads();
        stage_mma2(As, Bs, c, wm, wn, g, tg);
        __syncthreads();
    }

#pragma unroll
    for (int mt = 0; mt < 2; mt++)
#pragma unroll
        for (int nt = 0; nt < 8; nt++) {
            int r0 = wm + mt * 16 + g;
            int cc = bn + wn + nt * 8 + tg * 2;
            if (bm + r0 < cnt)
                *(float2*)(Cb + (ll)(off + bm + r0) * HIDN + cc)
                    = make_float2(c[mt][nt][0], c[mt][nt][1]);
            if (bm + r0 + 8 < cnt)
                *(float2*)(Cb + (ll)(off + bm + r0 + 8) * HIDN + cc)
                    = make_float2(c[mt][nt][2], c[mt][nt][3]);
        }
}

// ---------------- MoE down via mma2 ----------------
__global__ __launch_bounds__(256, 2) void moedown_mma(const float* __restrict__ w2, int l)
{
    const int e = blockIdx.z;
    const int cnt = g_counts[e];
    const int bm = blockIdx.y * 128;
    if (bm >= cnt) return;
    const int off = g_offs[e];
    const int bn = blockIdx.x * 128;

    const float* Bb = w2 + ((ll)l * EE + e) * HIDN * DD;

    extern __shared__ uint32_t sm[];
    uint32_t* As = sm;
    uint32_t* Bs = sm + 2 * MATW;

    const int tid = threadIdx.x, wid = tid >> 5, lane = tid & 31;
    const int g = lane >> 2, tg = lane & 3;
    const int wm = (wid >> 1) * 32, wn = (wid & 1) * 64;

    float c[2][8][4];
#pragma unroll
    for (int mt = 0; mt < 2; mt++)
#pragma unroll
        for (int nt = 0; nt < 8; nt++)
#pragma unroll
            for (int i = 0; i < 4; i++) c[mt][nt][i] = 0.f;

    for (int k0 = 0; k0 < HIDN; k0 += 32) {
#pragma unroll
        for (int i = 0; i < 4; i++) {
            int idx = tid + i * 256;
            int m = idx >> 3, qq = idx & 7;
            float4 v = make_float4(0.f, 0.f, 0.f, 0.f);
            if (bm + m < cnt)
                v = *(const float4*)(g_G + (ll)(off + bm + m) * HIDN + k0 + qq * 4);
            sts_split2(&As[m * LSTR + qq * 4], v);
        }
        loadBT_cf(Bb, DD, bn, k0, Bs, wid, lane);
        __syncthreads();
        stage_mma2(As, Bs, c, wm, wn, g, tg);
        __syncthreads();
    }

#pragma unroll
    for (int mt = 0; mt < 2; mt++)
#pragma unroll
        for (int nt = 0; nt < 8; nt++) {
            int r0 = wm + mt * 16 + g;
            int cc = bn + wn + nt * 8 + tg * 2;
            if (bm + r0 < cnt)
                *(float2*)(g_Y + (ll)(off + bm + r0) * DD + cc)
                    = make_float2(c[mt][nt][0], c[mt][nt][1]);
            if (bm + r0 + 8 < cnt)
                *(float2*)(g_Y + (ll)(off + bm + r0 + 8) * DD + cc)
                    = make_float2(c[mt][nt][2], c[mt][nt][3]);
        }
}

// ---------------- small kernels ----------------
__global__ void embed_kernel(const int* __restrict__ ids, const float* __restrict__ tok)
{
    int t = blockIdx.x;
    ll base = (ll)ids[t] * DD;
    for (int d = threadIdx.x; d < DD; d += blockDim.x)
        g_x[t * DD + d] = tok[base + d];
}

__global__ void rmsnorm_kernel(const float* __restrict__ x, const float* __restrict__ w,
                               float* __restrict__ out)
{
    int t = blockIdx.x, tid = threadIdx.x;
    __shared__ float red[256];
    float s = 0.f;
    for (int d = tid; d < DD; d += 256) { float v = x[t * DD + d]; s += v * v; }
    red[tid] = s; __syncthreads();
    for (int st = 128; st > 0; st >>= 1) {
        if (tid < st) red[tid] += red[tid + st];
        __syncthreads();
    }
    float r = rsqrtf(red[0] / (float)DD + 1e-6f);
    for (int d = tid; d < DD; d += 256)
        out[t * DD + d] = x[t * DD + d] * r * w[d];
}

__global__ void rope_kernel()
{
    int t = blockIdx.x, tid = threadIdx.x;
    int h = tid >> 5, i = tid & 31;
    float inv = powf(10000.f, -(float)i / 32.f);
    float ang = (float)t * inv;
    float c = cosf(ang), s = sinf(ang);
    int i1 = t * DD + h * HDD + i, i2 = i1 + 32;
    float q1 = g_q[i1], q2 = g_q[i2];
    g_q[i1] = q1 * c - q2 * s;
    g_q[i2] = q2 * c + q1 * s;
    float k1 = g_k[i1], k2 = g_k[i2];
    g_k[i1] = k1 * c - k2 * s;
    g_k[i2] = k2 * c + k1 * s;
}

__global__ void attn_softmax_kernel()
{
    int b = blockIdx.x;
    int h = b / TT, t = b % TT;
    float* row = g_P + (ll)h * TT * TT + (ll)t * TT;
    const float scale = 0.125f;
    __shared__ float red[128];
    int tid = threadIdx.x;

    float m = -3.4e38f;
    for (int s = tid; s <= t; s += 128) m = fmaxf(m, row[s] * scale);
    red[tid] = m; __syncthreads();
    for (int st = 64; st > 0; st >>= 1) {
        if (tid < st) red[tid] = fmaxf(red[tid], red[tid + st]);
        __syncthreads();
    }
    m = red[0]; __syncthreads();

    float sum = 0.f;
    for (int s = tid; s <= t; s += 128) {
        float e = expf(row[s] * scale - m);
        row[s] = e; sum += e;
    }
    red[tid] = sum; __syncthreads();
    for (int st = 64; st > 0; st >>= 1) {
        if (tid < st) red[tid] += red[tid + st];
        __syncthreads();
    }
    float inv = 1.f / red[0];
    for (int s = tid; s <= t; s += 128) row[s] *= inv;
    int zend = min(TT, ((t >> 7) + 1) << 7);
    for (int s = t + 1 + tid; s < zend; s += 128) row[s] = 0.f;
}

__global__ void zero_counts_kernel()
{
    if (threadIdx.x < EE) g_counts[threadIdx.x] = 0;
}

__global__ void router_kernel(const float* __restrict__ xn, const float* __restrict__ rw)
{
    int t = blockIdx.x, tid = threadIdx.x;
    __shared__ float part[EE][128];
    float loc[EE];
#pragma unroll
    for (int e = 0; e < EE; e++) loc[e] = 0.f;
    for (int d = tid; d < DD; d += 128) {
        float xv = xn[t * DD + d];
#pragma unroll
        for (int e = 0; e < EE; e++) loc[e] += xv * rw[d * EE + e];
    }
#pragma unroll
    for (int e = 0; e < EE; e++) part[e][tid] = loc[e];
    __syncthreads();
    for (int st = 64; st > 0; st >>= 1) {
        if (tid < st)
#pragma unroll
            for (int e = 0; e < EE; e++) part[e][tid] += part[e][tid + st];
        __syncthreads();
    }
    if (tid == 0) {
        float v0 = -3.4e38f, v1 = -3.4e38f;
        int i0 = 0, i1 = 0;
        for (int e = 0; e < EE; e++) {
            float v = part[e][0];
            if (v > v0) { v1 = v0; i1 = i0; v0 = v; i0 = e; }
            else if (v > v1) { v1 = v; i1 = e; }
        }
        float e1 = expf(v1 - v0);
        float inv = 1.f / (1.f + e1);
        g_eidx[t * 2]     = i0;  g_ew[t * 2]     = inv;
        g_eidx[t * 2 + 1] = i1;  g_ew[t * 2 + 1] = e1 * inv;
        atomicAdd(&g_counts[i0], 1);
        atomicAdd(&g_counts[i1], 1);
    }
}

__global__ void scan_kernel()
{
    int off = 0;
    for (int e = 0; e < EE; e++) {
        g_offs[e] = off;
        off += g_counts[e];
        g_cursor[e] = 0;
    }
}

__global__ void scatter_kernel()
{
    int idx = blockIdx.x * blockDim.x + threadIdx.x;
    if (idx >= TT * 2) return;
    int e = g_eidx[idx];
    int pos = g_offs[e] + atomicAdd(&g_cursor[e], 1);
    g_perm[pos] = idx >> 1;
    g_slot[idx] = pos;
}

__global__ void silu_mul_kernel()
{
    int i = blockIdx.x * blockDim.x + threadIdx.x;
    if (i >= TT * 2 * HIDN) return;
    float g = g_G[i];
    g_G[i] = (g / (1.f + expf(-g))) * g_U[i];
}

__global__ void combine_kernel()
{
    int i = blockIdx.x * blockDim.x + threadIdx.x;
    if (i >= TT * DD) return;
    int t = i / DD, d = i % DD;
    g_x[i] += g_ew[t * 2] * g_Y[(ll)g_slot[t * 2] * DD + d]
            + g_ew[t * 2 + 1] * g_Y[(ll)g_slot[t * 2 + 1] * DD + d];
}

// ---------------- orchestration ----------------
extern "C" void kernel_launch(void* const* d_in, const int* in_sizes, int n_in,
                              void* d_out, int out_size)
{
    const int*   ids     = (const int*)d_in[0];
    const float* tok     = (const float*)d_in[1];
    const float* attn_nw = (const float*)d_in[2];
    const float* wq      = (const float*)d_in[3];
    const float* wk      = (const float*)d_in[4];
    const float* wv      = (const float*)d_in[5];
    const float* wo      = (const float*)d_in[6];
    const float* moe_nw  = (const float*)d_in[7];
    const float* rw      = (const float*)d_in[8];
    const float* w1      = (const float*)d_in[9];
    const float* w2      = (const float*)d_in[10];
    const float* w3      = (const float*)d_in[11];
    const float* fnw     = (const float*)d_in[12];
    float*       out     = (float*)d_out;

    cudaFuncSetAttribute(mm_gemm2,    cudaFuncAttributeMaxDynamicSharedMemorySize, SMB2);
    cudaFuncSetAttribute(qkv_mma,     cudaFuncAttributeMaxDynamicSharedMemorySize, SMB2);
    cudaFuncSetAttribute(wo_mma,      cudaFuncAttributeMaxDynamicSharedMemorySize, SMB2);
    cudaFuncSetAttribute(score_mma,   cudaFuncAttributeMaxDynamicSharedMemorySize, SMB2);
    cudaFuncSetAttribute(moeup_mma,   cudaFuncAttributeMaxDynamicSharedMemorySize, SMB2);
    cudaFuncSetAttribute(moedown_mma, cudaFuncAttributeMaxDynamicSharedMemorySize, SMB2);

    float *x, *xn, *P, *v, *attn;
    cudaGetSymbolAddress((void**)&x,    g_x);
    cudaGetSymbolAddress((void**)&xn,   g_xn);
    cudaGetSymbolAddress((void**)&P,    g_P);
    cudaGetSymbolAddress((void**)&v,    g_v);
    cudaGetSymbolAddress((void**)&attn, g_attn);

    embed_kernel<<<TT, 256>>>(ids, tok);

    for (int l = 0; l < LLAY; l++) {
        rmsnorm_kernel<<<TT, 256>>>(x, attn_nw + (ll)l * DD, xn);

        qkv_mma<<<dim3(4, 16, 3), 256, SMB2>>>(xn, wq, wk, wv, l);
        rope_kernel<<<TT, 256>>>();

        score_mma<<<dim3(16, 16, HH), 256, SMB2>>>();
        attn_softmax_kernel<<<HH * TT, 128>>>();

        // PV on trusted fp32 path (router-critical precision)
        sgemm2<false><<<dim3(1, 16, HH), 256>>>(P, TT, (ll)TT * TT, v, DD, HDD,
                                                attn, DD, HDD, (const float*)0,
                                                TT, HDD, TT, FLAG_KCLIP);

        wo_mma<<<dim3(4, 16, 1), 256, SMB2>>>(wo, l);

        rmsnorm_kernel<<<TT, 256>>>(x, moe_nw + (ll)l * DD, xn);
        zero_counts_kernel<<<1, 32>>>();
        router_kernel<<<TT, 128>>>(xn, rw + (ll)l * DD * EE);
        scan_kernel<<<1, 1>>>();
        scatter_kernel<<<(TT * 2 + 255) / 256, 256>>>();

        moeup_mma<<<dim3(16, 16, 16), 256, SMB2>>>(xn, w1, w3, l);
        silu_mul_kernel<<<(TT * 2 * HIDN + 255) / 256, 256>>>();
        moedown_mma<<<dim3(4, 16, EE), 256, SMB2>>>(w2, l);
        combine_kernel<<<(TT * DD + 255) / 256, 256>>>();
    }

    rmsnorm_kernel<<<TT, 256>>>(x, fnw, xn);
    mm_gemm2<<<dim3(250, 16, 1), 256, SMB2>>>(xn, DD, tok, DD, out, VV, VV, DD);
}

// round 17
// speedup vs baseline: 1.0572x; 1.0572x over previous
#include <cuda_runtime.h>
#include <math.h>
#include <stdint.h>

#define TT   2048
#define DD   512
#define HH   8
#define HDD  64
#define LLAY 4
#define HIDN 2048
#define EE   8
#define VV   32000
typedef long long ll;
typedef unsigned long long ull;

// ---------------- device scratch ----------------
__device__ float g_x[TT * DD];
__device__ float g_xn[TT * DD];
__device__ float g_q[TT * DD];
__device__ float g_k[TT * DD];
__device__ float g_v[TT * DD];
__device__ float g_attn[TT * DD];
__device__ float g_P[(ll)HH * TT * TT];
__device__ float g_G[TT * 2 * HIDN];
__device__ float g_U[TT * 2 * HIDN];
__device__ float g_Y[TT * 2 * DD];
__device__ float g_ew[TT * 2];
__device__ int   g_eidx[TT * 2];
__device__ int   g_counts[EE];
__device__ int   g_offs[EE];
__device__ int   g_cursor[EE];
__device__ int   g_perm[TT * 2];
__device__ int   g_slot[TT * 2];

// ---------------- f32x2 fp32 PV path (bit-exact to R8 chain) ----------------
__device__ __forceinline__ ull pk2(float x) {
    ull r; uint32_t u = __float_as_uint(x);
    asm("mov.b64 %0, {%1, %1};" : "=l"(r) : "r"(u));
    return r;
}
__device__ __forceinline__ float2 up2(ull v) {
    uint32_t lo, hi;
    asm("mov.b64 {%0, %1}, %2;" : "=r"(lo), "=r"(hi) : "l"(v));
    return make_float2(__uint_as_float(lo), __uint_as_float(hi));
}
#define FMA2(c, a, b) asm("fma.rn.f32x2 %0, %1, %2, %0;" : "+l"(c) : "l"(a), "l"(b))

// 8 rows x 4 cols per thread; per-element fma chain identical to R15's micro8.
__device__ __forceinline__ void micro8h(
    const float (*As)[128], const float (*Bs)[128],
    ull c[8][2], int ty, int tx)
{
#pragma unroll
    for (int kk = 0; kk < 8; kk++) {
        const float* ar = &As[kk][ty * 8];
        const ull* br = (const ull*)&Bs[kk][tx * 4];
        ull b0 = br[0], b1 = br[1];
#pragma unroll
        for (int i = 0; i < 8; i++) {
            ull ap = pk2(ar[i]);
            FMA2(c[i][0], ap, b0);
            FMA2(c[i][1], ap, b1);
        }
    }
}

// PV: attn[:, h] = P_h @ v_h, K clipped to causal limit. N=64 exact tile.
__global__ __launch_bounds__(256, 2) void pv_f32()
{
    const int bm = blockIdx.y * 128;
    const int h = blockIdx.z;
    const float* Pb = g_P + (ll)h * TT * TT;
    const float* Vb = g_v + h * HDD;

    __shared__ __align__(16) float As[8][128];
    __shared__ __align__(16) float Bs[8][128];

    const int tid = threadIdx.x;
    const int tx = tid & 15, ty = tid >> 4;

    ull c[8][2];
#pragma unroll
    for (int i = 0; i < 8; i++) { c[i][0] = 0ull; c[i][1] = 0ull; }

    const int kmax = bm + 128;
    for (int k0 = 0; k0 < kmax; k0 += 8) {
#pragma unroll
        for (int i = 0; i < 4; i++) {
            int idx = tid + i * 256;
            int m = idx >> 3, kk = idx & 7;
            As[kk][m] = Pb[(ll)(bm + m) * TT + k0 + kk];
        }
#pragma unroll
        for (int i = 0; i < 4; i++) {
            int idx = tid + i * 256;
            int kk = idx >> 7, n = idx & 127;
            Bs[kk][n] = (n < HDD) ? Vb[(ll)(k0 + kk) * DD + n] : 0.f;
        }
        __syncthreads();
        micro8h(As, Bs, c, ty, tx);
        __syncthreads();
    }

#pragma unroll
    for (int i = 0; i < 8; i++) {
        int r = bm + ty * 8 + i;
        float2 v0 = up2(c[i][0]);
        float2 v1 = up2(c[i][1]);
        *(float2*)(g_attn + (ll)r * DD + h * HDD + tx * 4)     = v0;
        *(float2*)(g_attn + (ll)r * DD + h * HDD + tx * 4 + 2) = v1;
    }
}

// ================= 2-term split TF32 mma machinery (validated) =============
__device__ __forceinline__ uint32_t f2tf(float x) {
    uint32_t r;
    asm("cvt.rna.tf32.f32 %0, %1;" : "=r"(r) : "f"(x));
    return r;
}
#define LSTR 36
#define MATW (128 * LSTR)
#define SMB2 (4 * MATW * 4)          // A hi/lo + B hi/lo = 73728 B

__device__ __forceinline__ void sts_split2(uint32_t* p, float4 v) {
    uint32_t hx = f2tf(v.x), hy = f2tf(v.y), hz = f2tf(v.z), hw = f2tf(v.w);
    *(uint4*)p = make_uint4(hx, hy, hz, hw);
    uint4 lo;
    lo.x = f2tf(v.x - __uint_as_float(hx));
    lo.y = f2tf(v.y - __uint_as_float(hy));
    lo.z = f2tf(v.z - __uint_as_float(hz));
    lo.w = f2tf(v.w - __uint_as_float(hw));
    *(uint4*)(p + MATW) = lo;
}
__device__ __forceinline__ void sts_split1(uint32_t* p, float x) {
    uint32_t h = f2tf(x);
    p[0]    = h;
    p[MATW] = f2tf(x - __uint_as_float(h));
}
__device__ __forceinline__ void mma8(float* c, const uint32_t* a, const uint32_t* b) {
    asm volatile(
        "mma.sync.aligned.m16n8k8.row.col.f32.tf32.tf32.f32 "
        "{%0,%1,%2,%3}, {%4,%5,%6,%7}, {%8,%9}, {%0,%1,%2,%3};"
        : "+f"(c[0]), "+f"(c[1]), "+f"(c[2]), "+f"(c[3])
        : "r"(a[0]), "r"(a[1]), "r"(a[2]), "r"(a[3]), "r"(b[0]), "r"(b[1]));
}

// full 3-product stage (router-critical GEMMs)
__device__ __forceinline__ void stage_mma2(
    const uint32_t* As, const uint32_t* Bs, float c[2][8][4],
    int wm, int wn, int g, int tg)
{
#pragma unroll
    for (int kk = 0; kk < 32; kk += 8) {
        uint32_t ah[2][4], al[2][4];
#pragma unroll
        for (int mt = 0; mt < 2; mt++) {
            const uint32_t* p = &As[(wm + mt * 16 + g) * LSTR + kk + tg];
            ah[mt][0] = p[0];          ah[mt][2] = p[4];
            ah[mt][1] = p[8 * LSTR];   ah[mt][3] = p[8 * LSTR + 4];
            const uint32_t* q = p + MATW;
            al[mt][0] = q[0];          al[mt][2] = q[4];
            al[mt][1] = q[8 * LSTR];   al[mt][3] = q[8 * LSTR + 4];
        }
#pragma unroll
        for (int nt = 0; nt < 8; nt++) {
            const uint32_t* p = &Bs[(wn + nt * 8 + g) * LSTR + kk + tg];
            uint32_t bh[2], bl[2];
            bh[0] = p[0];        bh[1] = p[4];
            bl[0] = p[MATW];     bl[1] = p[MATW + 4];
#pragma unroll
            for (int mt = 0; mt < 2; mt++) {
                mma8(c[mt][nt], al[mt], bh);
                mma8(c[mt][nt], ah[mt], bl);
                mma8(c[mt][nt], ah[mt], bh);
            }
        }
    }
}

// 2-product stage for the LM head (output-final): drops al*bh (~2.8e-4 rel)
__device__ __forceinline__ void stage_mma2_lm(
    const uint32_t* As, const uint32_t* Bs, float c[2][8][4],
    int wm, int wn, int g, int tg)
{
#pragma unroll
    for (int kk = 0; kk < 32; kk += 8) {
        uint32_t ah[2][4];
#pragma unroll
        for (int mt = 0; mt < 2; mt++) {
            const uint32_t* p = &As[(wm + mt * 16 + g) * LSTR + kk + tg];
            ah[mt][0] = p[0];          ah[mt][2] = p[4];
            ah[mt][1] = p[8 * LSTR];   ah[mt][3] = p[8 * LSTR + 4];
        }
#pragma unroll
        for (int nt = 0; nt < 8; nt++) {
            const uint32_t* p = &Bs[(wn + nt * 8 + g) * LSTR + kk + tg];
            uint32_t bh[2], bl[2];
            bh[0] = p[0];        bh[1] = p[4];
            bl[0] = p[MATW];     bl[1] = p[MATW + 4];
#pragma unroll
            for (int mt = 0; mt < 2; mt++) {
                mma8(c[mt][nt], ah[mt], bl);
                mma8(c[mt][nt], ah[mt], bh);
            }
        }
    }
}

// Conflict-free transposed-B split store (validated R15)
__device__ __forceinline__ void loadBT_cf(
    const float* __restrict__ Bb, int ldb, int bn, int k0,
    uint32_t* Bs, int wid, int lane)
{
    const int kk = wid * 4 + (lane & 3);
    const int nb = lane >> 2;
    const float* src = Bb + (ll)(k0 + kk) * ldb + bn + nb;
    uint32_t* dst = &Bs[nb * LSTR + kk];
#pragma unroll
    for (int j = 0; j < 16; j++)
        sts_split1(dst + j * 8 * LSTR, src[j * 8]);
}

// ---------------- LM head (2-product mma) ----------------
__global__ __launch_bounds__(256) void mm_gemm2(
    const float* __restrict__ A, int lda,
    const float* __restrict__ BT, int ldb,
    float* __restrict__ C, int ldc, int N, int K)
{
    const int bm = blockIdx.y * 128, bn = blockIdx.x * 128;

    extern __shared__ uint32_t sm[];
    uint32_t* As = sm;
    uint32_t* Bs = sm + 2 * MATW;

    const int tid = threadIdx.x, wid = tid >> 5, lane = tid & 31;
    const int g = lane >> 2, tg = lane & 3;
    const int wm = (wid >> 1) * 32, wn = (wid & 1) * 64;

    float c[2][8][4];
#pragma unroll
    for (int mt = 0; mt < 2; mt++)
#pragma unroll
        for (int nt = 0; nt < 8; nt++)
#pragma unroll
            for (int i = 0; i < 4; i++) c[mt][nt][i] = 0.f;

    for (int k0 = 0; k0 < K; k0 += 32) {
#pragma unroll
        for (int i = 0; i < 4; i++) {
            int idx = tid + i * 256;
            int m = idx >> 3, qq = idx & 7;
            float4 v = *(const float4*)(A + (ll)(bm + m) * lda + k0 + qq * 4);
            sts_split2(&As[m * LSTR + qq * 4], v);
        }
#pragma unroll
        for (int i = 0; i < 4; i++) {
            int idx = tid + i * 256;
            int n = idx >> 3, qq = idx & 7;
            float4 v = make_float4(0.f, 0.f, 0.f, 0.f);
            if (bn + n < N) v = *(const float4*)(BT + (ll)(bn + n) * ldb + k0 + qq * 4);
            sts_split2(&Bs[n * LSTR + qq * 4], v);
        }
        __syncthreads();
        stage_mma2_lm(As, Bs, c, wm, wn, g, tg);
        __syncthreads();
    }

#pragma unroll
    for (int mt = 0; mt < 2; mt++)
#pragma unroll
        for (int nt = 0; nt < 8; nt++) {
            int r0 = bm + wm + mt * 16 + g;
            int cc = bn + wn + nt * 8 + tg * 2;
            if (cc < N) {
                *(float2*)(C + (ll)r0 * ldc + cc)       = make_float2(c[mt][nt][0], c[mt][nt][1]);
                *(float2*)(C + (ll)(r0 + 8) * ldc + cc) = make_float2(c[mt][nt][2], c[mt][nt][3]);
            }
        }
}

// ---------------- QKV via mma2 ----------------
__global__ __launch_bounds__(256) void qkv_mma(
    const float* __restrict__ xn,
    const float* __restrict__ wq, const float* __restrict__ wk,
    const float* __restrict__ wv, int l)
{
    const int z = blockIdx.z;
    const float* Bb = (z == 0 ? wq : z == 1 ? wk : wv) + (ll)l * DD * DD;
    float* Cb = (z == 0 ? g_q : z == 1 ? g_k : g_v);

    const int bm = blockIdx.y * 128, bn = blockIdx.x * 128;
    extern __shared__ uint32_t sm[];
    uint32_t* As = sm;
    uint32_t* Bs = sm + 2 * MATW;

    const int tid = threadIdx.x, wid = tid >> 5, lane = tid & 31;
    const int g = lane >> 2, tg = lane & 3;
    const int wm = (wid >> 1) * 32, wn = (wid & 1) * 64;

    float c[2][8][4];
#pragma unroll
    for (int mt = 0; mt < 2; mt++)
#pragma unroll
        for (int nt = 0; nt < 8; nt++)
#pragma unroll
            for (int i = 0; i < 4; i++) c[mt][nt][i] = 0.f;

    for (int k0 = 0; k0 < DD; k0 += 32) {
#pragma unroll
        for (int i = 0; i < 4; i++) {
            int idx = tid + i * 256;
            int m = idx >> 3, qq = idx & 7;
            float4 v = *(const float4*)(xn + (ll)(bm + m) * DD + k0 + qq * 4);
            sts_split2(&As[m * LSTR + qq * 4], v);
        }
        loadBT_cf(Bb, DD, bn, k0, Bs, wid, lane);
        __syncthreads();
        stage_mma2(As, Bs, c, wm, wn, g, tg);
        __syncthreads();
    }

#pragma unroll
    for (int mt = 0; mt < 2; mt++)
#pragma unroll
        for (int nt = 0; nt < 8; nt++) {
            int r0 = bm + wm + mt * 16 + g;
            int cc = bn + wn + nt * 8 + tg * 2;
            *(float2*)(Cb + (ll)r0 * DD + cc)       = make_float2(c[mt][nt][0], c[mt][nt][1]);
            *(float2*)(Cb + (ll)(r0 + 8) * DD + cc) = make_float2(c[mt][nt][2], c[mt][nt][3]);
        }
}

// ---------------- wo via mma2 (residual into g_x) ----------------
__global__ __launch_bounds__(256) void wo_mma(const float* __restrict__ wo, int l)
{
    const float* Bb = wo + (ll)l * DD * DD;
    const int bm = blockIdx.y * 128, bn = blockIdx.x * 128;
    extern __shared__ uint32_t sm[];
    uint32_t* As = sm;
    uint32_t* Bs = sm + 2 * MATW;

    const int tid = threadIdx.x, wid = tid >> 5, lane = tid & 31;
    const int g = lane >> 2, tg = lane & 3;
    const int wm = (wid >> 1) * 32, wn = (wid & 1) * 64;

    float c[2][8][4];
#pragma unroll
    for (int mt = 0; mt < 2; mt++)
#pragma unroll
        for (int nt = 0; nt < 8; nt++)
#pragma unroll
            for (int i = 0; i < 4; i++) c[mt][nt][i] = 0.f;

    for (int k0 = 0; k0 < DD; k0 += 32) {
#pragma unroll
        for (int i = 0; i < 4; i++) {
            int idx = tid + i * 256;
            int m = idx >> 3, qq = idx & 7;
            float4 v = *(const float4*)(g_attn + (ll)(bm + m) * DD + k0 + qq * 4);
            sts_split2(&As[m * LSTR + qq * 4], v);
        }
        loadBT_cf(Bb, DD, bn, k0, Bs, wid, lane);
        __syncthreads();
        stage_mma2(As, Bs, c, wm, wn, g, tg);
        __syncthreads();
    }

#pragma unroll
    for (int mt = 0; mt < 2; mt++)
#pragma unroll
        for (int nt = 0; nt < 8; nt++) {
            int r0 = bm + wm + mt * 16 + g;
            int cc = bn + wn + nt * 8 + tg * 2;
            float2* p0 = (float2*)(g_x + (ll)r0 * DD + cc);
            float2* p1 = (float2*)(g_x + (ll)(r0 + 8) * DD + cc);
            float2 v0 = *p0, v1 = *p1;
            v0.x += c[mt][nt][0]; v0.y += c[mt][nt][1];
            v1.x += c[mt][nt][2]; v1.y += c[mt][nt][3];
            *p0 = v0; *p1 = v1;
        }
}

// ---------------- attention scores via mma2 (causal block-skip) -------------
__global__ __launch_bounds__(256) void score_mma()
{
    const int bm = blockIdx.y * 128, bn = blockIdx.x * 128;
    if (bn > bm) return;
    const int h = blockIdx.z;
    const float* Aq = g_q + h * HDD;
    const float* Bk = g_k + h * HDD;
    float* P = g_P + (ll)h * TT * TT;

    extern __shared__ uint32_t sm[];
    uint32_t* As = sm;
    uint32_t* Bs = sm + 2 * MATW;

    const int tid = threadIdx.x, wid = tid >> 5, lane = tid & 31;
    const int g = lane >> 2, tg = lane & 3;
    const int wm = (wid >> 1) * 32, wn = (wid & 1) * 64;

    float c[2][8][4];
#pragma unroll
    for (int mt = 0; mt < 2; mt++)
#pragma unroll
        for (int nt = 0; nt < 8; nt++)
#pragma unroll
            for (int i = 0; i < 4; i++) c[mt][nt][i] = 0.f;

#pragma unroll
    for (int k0 = 0; k0 < HDD; k0 += 32) {
#pragma unroll
        for (int i = 0; i < 4; i++) {
            int idx = tid + i * 256;
            int m = idx >> 3, qq = idx & 7;
            float4 v = *(const float4*)(Aq + (ll)(bm + m) * DD + k0 + qq * 4);
            sts_split2(&As[m * LSTR + qq * 4], v);
        }
#pragma unroll
        for (int i = 0; i < 4; i++) {
            int idx = tid + i * 256;
            int n = idx >> 3, qq = idx & 7;
            float4 v = *(const float4*)(Bk + (ll)(bn + n) * DD + k0 + qq * 4);
            sts_split2(&Bs[n * LSTR + qq * 4], v);
        }
        __syncthreads();
        stage_mma2(As, Bs, c, wm, wn, g, tg);
        __syncthreads();
    }

#pragma unroll
    for (int mt = 0; mt < 2; mt++)
#pragma unroll
        for (int nt = 0; nt < 8; nt++) {
            int r0 = bm + wm + mt * 16 + g;
            int cc = bn + wn + nt * 8 + tg * 2;
            *(float2*)(P + (ll)r0 * TT + cc)       = make_float2(c[mt][nt][0], c[mt][nt][1]);
            *(float2*)(P + (ll)(r0 + 8) * TT + cc) = make_float2(c[mt][nt][2], c[mt][nt][3]);
        }
}

// ---------------- MoE up via mma2 ----------------
__global__ __launch_bounds__(256) void moeup_mma(
    const float* __restrict__ xn,
    const float* __restrict__ w1, const float* __restrict__ w3, int l)
{
    const int e = blockIdx.z >> 1, which = blockIdx.z & 1;
    const int cnt = g_counts[e];
    const int bm = blockIdx.y * 128;
    if (bm >= cnt) return;
    const int off = g_offs[e];
    const int bn = blockIdx.x * 128;

    const float* Bb = (which ? w3 : w1) + ((ll)l * EE + e) * DD * HIDN;
    float* Cb = which ? g_U : g_G;

    extern __shared__ uint32_t sm[];
    uint32_t* As = sm;
    uint32_t* Bs = sm + 2 * MATW;

    const int tid = threadIdx.x, wid = tid >> 5, lane = tid & 31;
    const int g = lane >> 2, tg = lane & 3;
    const int wm = (wid >> 1) * 32, wn = (wid & 1) * 64;

    const float* aptr[4];
    int av[4];
#pragma unroll
    for (int i = 0; i < 4; i++) {
        int m = (tid + i * 256) >> 3;
        av[i] = (bm + m) < cnt;
        aptr[i] = xn + (ll)(av[i] ? g_perm[off + bm + m] : 0) * DD;
    }

    float c[2][8][4];
#pragma unroll
    for (int mt = 0; mt < 2; mt++)
#pragma unroll
        for (int nt = 0; nt < 8; nt++)
#pragma unroll
            for (int i = 0; i < 4; i++) c[mt][nt][i] = 0.f;

    for (int k0 = 0; k0 < DD; k0 += 32) {
#pragma unroll
        for (int i = 0; i < 4; i++) {
            int idx = tid + i * 256;
            int m = idx >> 3, qq = idx & 7;
            float4 v = make_float4(0.f, 0.f, 0.f, 0.f);
            if (av[i]) v = *(const float4*)(aptr[i] + k0 + qq * 4);
            sts_split2(&As[m * LSTR + qq * 4], v);
        }
        loadBT_cf(Bb, HIDN, bn, k0, Bs, wid, lane);
        __syncthreads();
        stage_mma2(As, Bs, c, wm, wn, g, tg);
        __syncthreads();
    }

#pragma unroll
    for (int mt = 0; mt < 2; mt++)
#pragma unroll
        for (int nt = 0; nt < 8; nt++) {
            int r0 = wm + mt * 16 + g;
            int cc = bn + wn + nt * 8 + tg * 2;
            if (bm + r0 < cnt)
                *(float2*)(Cb + (ll)(off + bm + r0) * HIDN + cc)
                    = make_float2(c[mt][nt][0], c[mt][nt][1]);
            if (bm + r0 + 8 < cnt)
                *(float2*)(Cb + (ll)(off + bm + r0 + 8) * HIDN + cc)
                    = make_float2(c[mt][nt][2], c[mt][nt][3]);
        }
}

// ---------------- MoE down via mma2 ----------------
__global__ __launch_bounds__(256) void moedown_mma(const float* __restrict__ w2, int l)
{
    const int e = blockIdx.z;
    const int cnt = g_counts[e];
    const int bm = blockIdx.y * 128;
    if (bm >= cnt) return;
    const int off = g_offs[e];
    const int bn = blockIdx.x * 128;

    const float* Bb = w2 + ((ll)l * EE + e) * HIDN * DD;

    extern __shared__ uint32_t sm[];
    uint32_t* As = sm;
    uint32_t* Bs = sm + 2 * MATW;

    const int tid = threadIdx.x, wid = tid >> 5, lane = tid & 31;
    const int g = lane >> 2, tg = lane & 3;
    const int wm = (wid >> 1) * 32, wn = (wid & 1) * 64;

    float c[2][8][4];
#pragma unroll
    for (int mt = 0; mt < 2; mt++)
#pragma unroll
        for (int nt = 0; nt < 8; nt++)
#pragma unroll
            for (int i = 0; i < 4; i++) c[mt][nt][i] = 0.f;

    for (int k0 = 0; k0 < HIDN; k0 += 32) {
#pragma unroll
        for (int i = 0; i < 4; i++) {
            int idx = tid + i * 256;
            int m = idx >> 3, qq = idx & 7;
            float4 v = make_float4(0.f, 0.f, 0.f, 0.f);
            if (bm + m < cnt)
                v = *(const float4*)(g_G + (ll)(off + bm + m) * HIDN + k0 + qq * 4);
            sts_split2(&As[m * LSTR + qq * 4], v);
        }
        loadBT_cf(Bb, DD, bn, k0, Bs, wid, lane);
        __syncthreads();
        stage_mma2(As, Bs, c, wm, wn, g, tg);
        __syncthreads();
    }

#pragma unroll
    for (int mt = 0; mt < 2; mt++)
#pragma unroll
        for (int nt = 0; nt < 8; nt++) {
            int r0 = wm + mt * 16 + g;
            int cc = bn + wn + nt * 8 + tg * 2;
            if (bm + r0 < cnt)
                *(float2*)(g_Y + (ll)(off + bm + r0) * DD + cc)
                    = make_float2(c[mt][nt][0], c[mt][nt][1]);
            if (bm + r0 + 8 < cnt)
                *(float2*)(g_Y + (ll)(off + bm + r0 + 8) * DD + cc)
                    = make_float2(c[mt][nt][2], c[mt][nt][3]);
        }
}

// ---------------- small kernels ----------------
__global__ void embed_kernel(const int* __restrict__ ids, const float* __restrict__ tok)
{
    int t = blockIdx.x;
    ll base = (ll)ids[t] * DD;
    for (int d = threadIdx.x; d < DD; d += blockDim.x)
        g_x[t * DD + d] = tok[base + d];
}

__global__ void rmsnorm_kernel(const float* __restrict__ x, const float* __restrict__ w,
                               float* __restrict__ out)
{
    int t = blockIdx.x, tid = threadIdx.x;
    __shared__ float red[256];
    float s = 0.f;
    for (int d = tid; d < DD; d += 256) { float v = x[t * DD + d]; s += v * v; }
    red[tid] = s; __syncthreads();
    for (int st = 128; st > 0; st >>= 1) {
        if (tid < st) red[tid] += red[tid + st];
        __syncthreads();
    }
    float r = rsqrtf(red[0] / (float)DD + 1e-6f);
    for (int d = tid; d < DD; d += 256)
        out[t * DD + d] = x[t * DD + d] * r * w[d];
}

__global__ void rope_kernel()
{
    int t = blockIdx.x, tid = threadIdx.x;
    int h = tid >> 5, i = tid & 31;
    float inv = powf(10000.f, -(float)i / 32.f);
    float ang = (float)t * inv;
    float c = cosf(ang), s = sinf(ang);
    int i1 = t * DD + h * HDD + i, i2 = i1 + 32;
    float q1 = g_q[i1], q2 = g_q[i2];
    g_q[i1] = q1 * c - q2 * s;
    g_q[i2] = q2 * c + q1 * s;
    float k1 = g_k[i1], k2 = g_k[i2];
    g_k[i1] = k1 * c - k2 * s;
    g_k[i2] = k2 * c + k1 * s;
}

__global__ void attn_softmax_kernel()
{
    int b = blockIdx.x;
    int h = b / TT, t = b % TT;
    float* row = g_P + (ll)h * TT * TT + (ll)t * TT;
    const float scale = 0.125f;
    __shared__ float red[128];
    int tid = threadIdx.x;

    float m = -3.4e38f;
    for (int s = tid; s <= t; s += 128) m = fmaxf(m, row[s] * scale);
    red[tid] = m; __syncthreads();
    for (int st = 64; st > 0; st >>= 1) {
        if (tid < st) red[tid] = fmaxf(red[tid], red[tid + st]);
        __syncthreads();
    }
    m = red[0]; __syncthreads();

    float sum = 0.f;
    for (int s = tid; s <= t; s += 128) {
        float e = expf(row[s] * scale - m);
        row[s] = e; sum += e;
    }
    red[tid] = sum; __syncthreads();
    for (int st = 64; st > 0; st >>= 1) {
        if (tid < st) red[tid] += red[tid + st];
        __syncthreads();
    }
    float inv = 1.f / red[0];
    for (int s = tid; s <= t; s += 128) row[s] *= inv;
    int zend = min(TT, ((t >> 7) + 1) << 7);
    for (int s = t + 1 + tid; s < zend; s += 128) row[s] = 0.f;
}

__global__ void zero_counts_kernel()
{
    if (threadIdx.x < EE) g_counts[threadIdx.x] = 0;
}

__global__ void router_kernel(const float* __restrict__ xn, const float* __restrict__ rw)
{
    int t = blockIdx.x, tid = threadIdx.x;
    __shared__ float part[EE][128];
    float loc[EE];
#pragma unroll
    for (int e = 0; e < EE; e++) loc[e] = 0.f;
    for (int d = tid; d < DD; d += 128) {
        float xv = xn[t * DD + d];
#pragma unroll
        for (int e = 0; e < EE; e++) loc[e] += xv * rw[d * EE + e];
    }
#pragma unroll
    for (int e = 0; e < EE; e++) part[e][tid] = loc[e];
    __syncthreads();
    for (int st = 64; st > 0; st >>= 1) {
        if (tid < st)
#pragma unroll
            for (int e = 0; e < EE; e++) part[e][tid] += part[e][tid + st];
        __syncthreads();
    }
    if (tid == 0) {
        float v0 = -3.4e38f, v1 = -3.4e38f;
        int i0 = 0, i1 = 0;
        for (int e = 0; e < EE; e++) {
            float v = part[e][0];
            if (v > v0) { v1 = v0; i1 = i0; v0 = v; i0 = e; }
            else if (v > v1) { v1 = v; i1 = e; }
        }
        float e1 = expf(v1 - v0);
        float inv = 1.f / (1.f + e1);
        g_eidx[t * 2]     = i0;  g_ew[t * 2]     = inv;
        g_eidx[t * 2 + 1] = i1;  g_ew[t * 2 + 1] = e1 * inv;
        atomicAdd(&g_counts[i0], 1);
        atomicAdd(&g_counts[i1], 1);
    }
}

__global__ void scan_kernel()
{
    int off = 0;
    for (int e = 0; e < EE; e++) {
        g_offs[e] = off;
        off += g_counts[e];
        g_cursor[e] = 0;
    }
}

__global__ void scatter_kernel()
{
    int idx = blockIdx.x * blockDim.x + threadIdx.x;
    if (idx >= TT * 2) return;
    int e = g_eidx[idx];
    int pos = g_offs[e] + atomicAdd(&g_cursor[e], 1);
    g_perm[pos] = idx >> 1;
    g_slot[idx] = pos;
}

__global__ void silu_mul_kernel()
{
    int i = blockIdx.x * blockDim.x + threadIdx.x;
    if (i >= TT * 2 * HIDN) return;
    float g = g_G[i];
    g_G[i] = (g / (1.f + expf(-g))) * g_U[i];
}

__global__ void combine_kernel()
{
    int i = blockIdx.x * blockDim.x + threadIdx.x;
    if (i >= TT * DD) return;
    int t = i / DD, d = i % DD;
    g_x[i] += g_ew[t * 2] * g_Y[(ll)g_slot[t * 2] * DD + d]
            + g_ew[t * 2 + 1] * g_Y[(ll)g_slot[t * 2 + 1] * DD + d];
}

// ---------------- orchestration ----------------
extern "C" void kernel_launch(void* const* d_in, const int* in_sizes, int n_in,
                              void* d_out, int out_size)
{
    const int*   ids     = (const int*)d_in[0];
    const float* tok     = (const float*)d_in[1];
    const float* attn_nw = (const float*)d_in[2];
    const float* wq      = (const float*)d_in[3];
    const float* wk      = (const float*)d_in[4];
    const float* wv      = (const float*)d_in[5];
    const float* wo      = (const float*)d_in[6];
    const float* moe_nw  = (const float*)d_in[7];
    const float* rw      = (const float*)d_in[8];
    const float* w1      = (const float*)d_in[9];
    const float* w2      = (const float*)d_in[10];
    const float* w3      = (const float*)d_in[11];
    const float* fnw     = (const float*)d_in[12];
    float*       out     = (float*)d_out;

    cudaFuncSetAttribute(mm_gemm2,    cudaFuncAttributeMaxDynamicSharedMemorySize, SMB2);
    cudaFuncSetAttribute(qkv_mma,     cudaFuncAttributeMaxDynamicSharedMemorySize, SMB2);
    cudaFuncSetAttribute(wo_mma,      cudaFuncAttributeMaxDynamicSharedMemorySize, SMB2);
    cudaFuncSetAttribute(score_mma,   cudaFuncAttributeMaxDynamicSharedMemorySize, SMB2);
    cudaFuncSetAttribute(moeup_mma,   cudaFuncAttributeMaxDynamicSharedMemorySize, SMB2);
    cudaFuncSetAttribute(moedown_mma, cudaFuncAttributeMaxDynamicSharedMemorySize, SMB2);

    float *x, *xn;
    cudaGetSymbolAddress((void**)&x,  g_x);
    cudaGetSymbolAddress((void**)&xn, g_xn);

    embed_kernel<<<TT, 256>>>(ids, tok);

    for (int l = 0; l < LLAY; l++) {
        rmsnorm_kernel<<<TT, 256>>>(x, attn_nw + (ll)l * DD, xn);

        qkv_mma<<<dim3(4, 16, 3), 256, SMB2>>>(xn, wq, wk, wv, l);
        rope_kernel<<<TT, 256>>>();

        score_mma<<<dim3(16, 16, HH), 256, SMB2>>>();
        attn_softmax_kernel<<<HH * TT, 128>>>();

        // PV: dedicated fp32 kernel, bit-exact chain (router-critical)
        pv_f32<<<dim3(1, 16, HH), 256>>>();

        wo_mma<<<dim3(4, 16, 1), 256, SMB2>>>(wo, l);

        rmsnorm_kernel<<<TT, 256>>>(x, moe_nw + (ll)l * DD, xn);
        zero_counts_kernel<<<1, 32>>>();
        router_kernel<<<TT, 128>>>(xn, rw + (ll)l * DD * EE);
        scan_kernel<<<1, 1>>>();
        scatter_kernel<<<(TT * 2 + 255) / 256, 256>>>();

        moeup_mma<<<dim3(16, 16, 16), 256, SMB2>>>(xn, w1, w3, l);
        silu_mul_kernel<<<(TT * 2 * HIDN + 255) / 256, 256>>>();
        moedown_mma<<<dim3(4, 16, EE), 256, SMB2>>>(w2, l);
        combine_kernel<<<(TT * DD + 255) / 256, 256>>>();
    }

    rmsnorm_kernel<<<TT, 256>>>(x, fnw, xn);
    mm_gemm2<<<dim3(250, 16, 1), 256, SMB2>>>(xn, DD, tok, DD, out, VV, VV, DD);
}